// round 16
// baseline (speedup 1.0000x reference)
#include <cuda_runtime.h>
#include <cuda_fp16.h>
#include <math.h>
#include <stdint.h>

#define NTOK  197
#define BATCH 256
#define CDIM  768
#define NH    12
#define HD    64
#define LKEEP 98
#define NP    (NTOK - 1)     // 196
#define NNEW  (LKEEP + 2)    // 100
#define M1    (NTOK * BATCH) // 50432
#define M2    (NNEW * BATCH) // 25600

typedef __half f16;

// ---------------- scratch (device globals; no cudaMalloc allowed) ----------
__device__ float g_ln1 [(size_t)M1 * CDIM];          // fp32 (cls path)
__device__ float g_xres[(size_t)M1 * CDIM];
__device__ float g_cls [(size_t)BATCH * NP];
__device__ int   g_idx [BATCH * LKEEP];
__device__ int   g_comp[BATCH * LKEEP];
__device__ float g_xnew[(size_t)M2 * CDIM];

__device__ f16 g_ln1f[(size_t)M1 * CDIM];
__device__ f16 g_qkvf[(size_t)M1 * 3 * CDIM];
__device__ f16 g_attf[(size_t)M1 * CDIM];
__device__ f16 g_ln2f[(size_t)M2 * CDIM];
__device__ f16 g_fcf [(size_t)M2 * 4 * CDIM];
// weights concatenated: in_w | out_w | fc_w | pj_w  (single fp16)
#define O_INW 0
#define O_OW  (3 * CDIM * CDIM)
#define O_FCW (O_OW + CDIM * CDIM)
#define O_PJW (O_FCW + 4 * CDIM * CDIM)
#define W_TOT (O_PJW + 4 * CDIM * CDIM)
__device__ f16 g_wf[W_TOT];

// ---------------- helpers ----------------------------------------------------
__device__ __forceinline__ uint32_t smem_u32(const void* p) {
    uint32_t a;
    asm("{ .reg .u64 t; cvta.to.shared.u64 t, %1; cvt.u32.u64 %0, t; }"
        : "=r"(a) : "l"(p));
    return a;
}
__device__ __forceinline__ void ldsm4(uint32_t r[4], uint32_t addr) {
    asm volatile("ldmatrix.sync.aligned.m8n8.x4.shared.b16 {%0,%1,%2,%3}, [%4];"
        : "=r"(r[0]), "=r"(r[1]), "=r"(r[2]), "=r"(r[3]) : "r"(addr));
}
__device__ __forceinline__ void ldsm4t(uint32_t r[4], uint32_t addr) {
    asm volatile("ldmatrix.sync.aligned.m8n8.x4.trans.shared.b16 {%0,%1,%2,%3}, [%4];"
        : "=r"(r[0]), "=r"(r[1]), "=r"(r[2]), "=r"(r[3]) : "r"(addr));
}
__device__ __forceinline__ void mma_f16(float c[4], const uint32_t a[4],
                                        const uint32_t b[2]) {
    asm volatile("mma.sync.aligned.m16n8k16.row.col.f32.f16.f16.f32 "
        "{%0,%1,%2,%3}, {%4,%5,%6,%7}, {%8,%9}, {%0,%1,%2,%3};"
        : "+f"(c[0]), "+f"(c[1]), "+f"(c[2]), "+f"(c[3])
        : "r"(a[0]), "r"(a[1]), "r"(a[2]), "r"(a[3]), "r"(b[0]), "r"(b[1]));
}
__device__ __forceinline__ void cp16(uint32_t dst, const void* src) {
    asm volatile("cp.async.cg.shared.global [%0], [%1], 16;"
                 :: "r"(dst), "l"(src));
}
__device__ __forceinline__ uint32_t pack_h2(float a, float b) {
    __half2 h = __floats2half2_rn(a, b);
    return *reinterpret_cast<uint32_t*>(&h);
}
__device__ __forceinline__ uint32_t ex2_h2(uint32_t x) {
    uint32_t r;
    asm("ex2.approx.f16x2 %0, %1;" : "=r"(r) : "r"(x));
    return r;
}
__device__ __forceinline__ uint32_t tanh_h2(uint32_t x) {
    uint32_t r;
    asm("tanh.approx.f16x2 %0, %1;" : "=r"(r) : "r"(x));
    return r;
}
// fp32 fallback quick_gelu (only used on fp32-output act path, unused here)
__device__ __forceinline__ float qgelu(float x) {
    float t;
    asm("tanh.approx.f32 %0, %1;" : "=f"(t) : "f"(0.851f * x));
    return x * 0.5f * (1.f + t);
}

// ---------------- fp32 -> fp16 converter -------------------------------------
__global__ void convert_w_kernel(const float* __restrict__ s,
                                 f16* __restrict__ d, int n4)
{
    const int i = blockIdx.x * 256 + threadIdx.x;
    if (i >= n4) return;
    float4 v = ((const float4*)s)[i];
    ((__half2*)d)[2 * i]     = __floats2half2_rn(v.x, v.y);
    ((__half2*)d)[2 * i + 1] = __floats2half2_rn(v.z, v.w);
}

// ---------------- layernorm: one block per row of 768 ----------------------
__global__ void ln_kernel(const float* __restrict__ x,
                          const float* __restrict__ gam,
                          const float* __restrict__ bet,
                          float* __restrict__ y,
                          f16* __restrict__ yf)
{
    const int row = blockIdx.x;
    const int t   = threadIdx.x;
    const float* xr = x + (size_t)row * CDIM;

    float v0 = xr[t], v1 = xr[t + 256], v2 = xr[t + 512];
    float s  = v0 + v1 + v2;
    float ss = v0 * v0 + v1 * v1 + v2 * v2;

    __shared__ float red[16];
    #pragma unroll
    for (int o = 16; o; o >>= 1) {
        s  += __shfl_xor_sync(0xffffffffu, s,  o);
        ss += __shfl_xor_sync(0xffffffffu, ss, o);
    }
    const int warp = t >> 5, lane = t & 31;
    if (lane == 0) { red[warp] = s; red[warp + 8] = ss; }
    __syncthreads();
    float S = 0.f, SS = 0.f;
    #pragma unroll
    for (int i = 0; i < 8; i++) { S += red[i]; SS += red[i + 8]; }

    const float mu  = S * (1.f / CDIM);
    const float var = SS * (1.f / CDIM) - mu * mu;
    const float inv = rsqrtf(var + 1e-5f);

    const size_t base = (size_t)row * CDIM;
    #pragma unroll
    for (int e = 0; e < 3; e++) {
        const int c = t + e * 256;
        const float v = (e == 0 ? v0 : (e == 1 ? v1 : v2));
        const float o = (v - mu) * inv * gam[c] + bet[c];
        if (y) y[base + c] = o;
        yf[base + c] = __float2half_rn(o);
    }
}

// ---------------- fp16 mma.sync GEMM, 4-stage cp.async pipeline -------------
#define ROWB   80
#define TBYTES (128 * ROWB)
#define STG    (2 * TBYTES)
#define NSTAGE 4
#define GSM    (NSTAGE * STG)

__global__ void __launch_bounds__(256, 2)
f16_gemm_kernel(const f16* __restrict__ Af, const f16* __restrict__ Wf,
                const float* __restrict__ bias, const float* __restrict__ res,
                float* __restrict__ Cf, f16* __restrict__ Ch,
                int M, int Nn, int K, int act)
{
    extern __shared__ char dsm[];
    const uint32_t sb = smem_u32(dsm);

    const int tid = threadIdx.x, lane = tid & 31, wid = tid >> 5;
    const int wm = wid >> 2, wn = wid & 3;
    const int m0 = blockIdx.y * 128, n0 = blockIdx.x * 128;

    float acc[4][4][4] = {};

    auto issue = [&](int s, int t) {
        const int k0 = t << 5;
        #pragma unroll
        for (int r = 0; r < 4; r++) {
            const int id = tid + (r << 8);
            const int tensor = id >> 9;
            const int w = id & 511;
            const int row = w >> 2, c4 = w & 3;
            const f16* src = (tensor == 0)
                ? Af + (size_t)(m0 + row) * K + k0 + c4 * 8
                : Wf + (size_t)(n0 + row) * K + k0 + c4 * 8;
            const uint32_t dst = sb + (uint32_t)(s * STG + tensor * TBYTES
                                                 + row * ROWB + c4 * 16);
            cp16(dst, src);
        }
        asm volatile("cp.async.commit_group;" ::: "memory");
    };

    const int nch = K >> 5;
    issue(0, 0);
    issue(1, 1);
    issue(2, 2);

    for (int t = 0; t < nch; t++) {
        asm volatile("cp.async.wait_group 2;" ::: "memory");
        __syncthreads();
        if (t + 3 < nch) issue((t + 3) % NSTAGE, t + 3);
        else asm volatile("cp.async.commit_group;" ::: "memory");

        const uint32_t sA = sb + (uint32_t)((t % NSTAGE) * STG);
        #pragma unroll
        for (int ks = 0; ks < 2; ks++) {
            uint32_t ah[4][4];
            #pragma unroll
            for (int mf = 0; mf < 4; mf++) {
                const uint32_t ra = sA +
                    (uint32_t)((wm * 64 + mf * 16 + (lane & 15)) * ROWB
                               + ks * 32 + ((lane >> 4) << 4));
                ldsm4(ah[mf], ra);
            }
            #pragma unroll
            for (int pair = 0; pair < 2; pair++) {
                uint32_t bh4[4];
                const uint32_t rb = sA + TBYTES +
                    (uint32_t)((wn * 32 + pair * 16 + (lane & 7)
                                + ((lane >> 4) << 3)) * ROWB
                               + ks * 32 + (((lane >> 3) & 1) << 4));
                ldsm4(bh4, rb);
                #pragma unroll
                for (int mf = 0; mf < 4; mf++) {
                    mma_f16(acc[mf][pair * 2],     ah[mf], bh4);
                    mma_f16(acc[mf][pair * 2 + 1], ah[mf], bh4 + 2);
                }
            }
        }
    }

    #pragma unroll
    for (int mf = 0; mf < 4; mf++) {
        #pragma unroll
        for (int nf = 0; nf < 4; nf++) {
            const int rr = m0 + wm * 64 + mf * 16 + (lane >> 2);
            const int cc = n0 + wn * 32 + nf * 8 + ((lane & 3) << 1);
            const float b0 = bias[cc], b1 = bias[cc + 1];
            float v0 = acc[mf][nf][0] + b0;
            float v1 = acc[mf][nf][1] + b1;
            float v2 = acc[mf][nf][2] + b0;
            float v3 = acc[mf][nf][3] + b1;
            const size_t o0 = (size_t)rr * Nn + cc;
            const size_t o1 = (size_t)(rr + 8) * Nn + cc;
            if (Cf) {
                if (act) { v0 = qgelu(v0); v1 = qgelu(v1);
                           v2 = qgelu(v2); v3 = qgelu(v3); }
                if (res) {
                    float2 r0 = *(const float2*)(res + o0);
                    float2 r1 = *(const float2*)(res + o1);
                    v0 += r0.x; v1 += r0.y; v2 += r1.x; v3 += r1.y;
                }
                float2 s0; s0.x = v0; s0.y = v1;
                float2 s1; s1.x = v2; s1.y = v3;
                *(float2*)(Cf + o0) = s0;
                *(float2*)(Cf + o1) = s1;
            } else if (act) {
                // quick_gelu in packed fp16: x*0.5*(1+tanh(0.851x)), 1 MUFU/2 elems
                const uint32_t t01 = tanh_h2(pack_h2(0.851f * v0, 0.851f * v1));
                const uint32_t t23 = tanh_h2(pack_h2(0.851f * v2, 0.851f * v3));
                const __half2 h05 = __float2half2_rn(0.5f);
                const __half2 s01 = __hfma2(*(const __half2*)&t01, h05, h05);
                const __half2 s23 = __hfma2(*(const __half2*)&t23, h05, h05);
                *(__half2*)(Ch + o0) = __hmul2(__floats2half2_rn(v0, v1), s01);
                *(__half2*)(Ch + o1) = __hmul2(__floats2half2_rn(v2, v3), s23);
            } else {
                *(__half2*)(Ch + o0) = __floats2half2_rn(v0, v1);
                *(__half2*)(Ch + o1) = __floats2half2_rn(v2, v3);
            }
        }
    }
}

// ---------------- tensor-core attention: one CTA per (b,h) ------------------
// softmax exp in packed fp16 (ex2.approx.f16x2): 1 MUFU per 2 probabilities.
#define TP   208
#define QP   72
#define ATT_SMEM (3 * TP * QP * 2)     // 89856 bytes

__global__ void __launch_bounds__(256)
attn_kernel(const f16* __restrict__ qkvf, f16* __restrict__ outf)
{
    extern __shared__ f16 smh[];
    f16* Qs = smh;
    f16* Ks = Qs + TP * QP;
    f16* Vs = Ks + TP * QP;

    const int b = blockIdx.x, h = blockIdx.y;
    const int tid = threadIdx.x, lane = tid & 31, warp = tid >> 5;
    const uint32_t sQ = smem_u32(Qs), sK = smem_u32(Ks), sV = smem_u32(Vs);

    for (int it = tid; it < TP * 8 * 3; it += 256) {
        const int t = it / (TP * 8);
        const int rem = it % (TP * 8);
        const int j = rem >> 3, c = rem & 7;
        f16* dst = (t == 0 ? Qs : (t == 1 ? Ks : Vs)) + j * QP + c * 8;
        if (j < NTOK) {
            const f16* src = qkvf + ((size_t)j * BATCH + b) * (3 * CDIM)
                             + t * CDIM + h * HD + c * 8;
            *(uint4*)dst = *(const uint4*)src;
        } else {
            uint4 z; z.x = z.y = z.z = z.w = 0u;
            *(uint4*)dst = z;
        }
    }
    __syncthreads();

    for (int mt = warp; mt < 13; mt += 8) {
        const int mbase = mt * 16;

        uint32_t aq[4][4];
        #pragma unroll
        for (int ks = 0; ks < 4; ks++) {
            const uint32_t ra = sQ + (uint32_t)(((mbase + (lane & 15)) * QP
                                + ks * 16 + ((lane >> 4) << 3)) * 2);
            ldsm4(aq[ks], ra);
        }

        float sacc[26][4];
        #pragma unroll
        for (int nt = 0; nt < 26; nt++)
            #pragma unroll
            for (int q = 0; q < 4; q++) sacc[nt][q] = 0.f;
        #pragma unroll
        for (int np = 0; np < 13; np++) {
            #pragma unroll
            for (int ks = 0; ks < 4; ks++) {
                uint32_t bk[4];
                const uint32_t rb = sK + (uint32_t)(((np * 16 + (lane & 7)
                                    + ((lane >> 4) << 3)) * QP
                                    + ks * 16 + (((lane >> 3) & 1) << 3)) * 2);
                ldsm4(bk, rb);
                mma_f16(sacc[np * 2],     aq[ks], bk);
                mma_f16(sacc[np * 2 + 1], aq[ks], bk + 2);
            }
        }

        float mx0 = -1e30f, mx1 = -1e30f;
        #pragma unroll
        for (int nt = 0; nt < 26; nt++) {
            const int c = nt * 8 + ((lane & 3) << 1);
            sacc[nt][0] = (c     < NTOK) ? sacc[nt][0] * 0.125f : -1e30f;
            sacc[nt][1] = (c + 1 < NTOK) ? sacc[nt][1] * 0.125f : -1e30f;
            sacc[nt][2] = (c     < NTOK) ? sacc[nt][2] * 0.125f : -1e30f;
            sacc[nt][3] = (c + 1 < NTOK) ? sacc[nt][3] * 0.125f : -1e30f;
            mx0 = fmaxf(mx0, fmaxf(sacc[nt][0], sacc[nt][1]));
            mx1 = fmaxf(mx1, fmaxf(sacc[nt][2], sacc[nt][3]));
        }
        mx0 = fmaxf(mx0, __shfl_xor_sync(0xffffffffu, mx0, 1));
        mx0 = fmaxf(mx0, __shfl_xor_sync(0xffffffffu, mx0, 2));
        mx1 = fmaxf(mx1, __shfl_xor_sync(0xffffffffu, mx1, 1));
        mx1 = fmaxf(mx1, __shfl_xor_sync(0xffffffffu, mx1, 2));

        // exp in f16x2: e = 2^((s-mx)*log2e); masked lanes -> -inf -> 0
        const float L2E = 1.4426950408889634f;
        uint32_t pe[26][2];
        float sm0 = 0.f, sm1 = 0.f;
        #pragma unroll
        for (int nt = 0; nt < 26; nt++) {
            const uint32_t e01 = ex2_h2(pack_h2((sacc[nt][0] - mx0) * L2E,
                                                (sacc[nt][1] - mx0) * L2E));
            const uint32_t e23 = ex2_h2(pack_h2((sacc[nt][2] - mx1) * L2E,
                                                (sacc[nt][3] - mx1) * L2E));
            pe[nt][0] = e01; pe[nt][1] = e23;
            const float2 f01 = __half22float2(*(const __half2*)&e01);
            const float2 f23 = __half22float2(*(const __half2*)&e23);
            sm0 += f01.x + f01.y;
            sm1 += f23.x + f23.y;
        }
        sm0 += __shfl_xor_sync(0xffffffffu, sm0, 1);
        sm0 += __shfl_xor_sync(0xffffffffu, sm0, 2);
        sm1 += __shfl_xor_sync(0xffffffffu, sm1, 1);
        sm1 += __shfl_xor_sync(0xffffffffu, sm1, 2);
        const __half2 iv0 = __float2half2_rn(1.f / sm0);
        const __half2 iv1 = __float2half2_rn(1.f / sm1);

        float oacc[8][4];
        #pragma unroll
        for (int nt = 0; nt < 8; nt++)
            #pragma unroll
            for (int q = 0; q < 4; q++) oacc[nt][q] = 0.f;
        #pragma unroll
        for (int kt = 0; kt < 13; kt++) {
            uint32_t ap[4];
            __half2 hv;
            hv = __hmul2(*(const __half2*)&pe[2 * kt][0],     iv0);
            ap[0] = *(const uint32_t*)&hv;
            hv = __hmul2(*(const __half2*)&pe[2 * kt][1],     iv1);
            ap[1] = *(const uint32_t*)&hv;
            hv = __hmul2(*(const __half2*)&pe[2 * kt + 1][0], iv0);
            ap[2] = *(const uint32_t*)&hv;
            hv = __hmul2(*(const __half2*)&pe[2 * kt + 1][1], iv1);
            ap[3] = *(const uint32_t*)&hv;
            #pragma unroll
            for (int np = 0; np < 4; np++) {
                uint32_t bv[4];
                const uint32_t va = sV + (uint32_t)(((kt * 16 + (lane & 15)) * QP
                                    + np * 16 + ((lane >> 4) << 3)) * 2);
                ldsm4t(bv, va);
                mma_f16(oacc[np * 2],     ap, bv);
                mma_f16(oacc[np * 2 + 1], ap, bv + 2);
            }
        }

        const int r0 = mbase + (lane >> 2), r1 = r0 + 8;
        #pragma unroll
        for (int nt = 0; nt < 8; nt++) {
            const int c = h * HD + nt * 8 + ((lane & 3) << 1);
            if (r0 < NTOK)
                *(__half2*)(outf + ((size_t)r0 * BATCH + b) * CDIM + c) =
                    __floats2half2_rn(oacc[nt][0], oacc[nt][1]);
            if (r1 < NTOK)
                *(__half2*)(outf + ((size_t)r1 * BATCH + b) * CDIM + c) =
                    __floats2half2_rn(oacc[nt][2], oacc[nt][3]);
        }
    }
}

// ---------------- CLS scores (fp64, all heads single-pass) + fused top-k ----
#define CLS_SMEM (((NH * HD) + (NH * CDIM) + (NH * NTOK) + NH + 8) * 8 \
                  + (CDIM + NP) * 4)

__global__ void __launch_bounds__(256)
cls_score_kernel(const float* __restrict__ ln1, const float* __restrict__ inw,
                 const float* __restrict__ inb, float* __restrict__ cls,
                 int* __restrict__ idx, int* __restrict__ comp)
{
    extern __shared__ double dsm2[];
    double* q0a  = dsm2;                 // [NH][HD]
    double* wv   = q0a + NH * HD;        // [NH][CDIM]
    double* sj   = wv + NH * CDIM;       // [NH][NTOK]
    double* beta = sj + NH * NTOK;       // [NH]
    double* redd = beta + NH;            // [8]
    float*  ln0  = (float*)(redd + 8);   // [CDIM]
    float*  cv   = ln0 + CDIM;           // [NP]

    const int b = blockIdx.x, tid = threadIdx.x;
    const int lane = tid & 31, w = tid >> 5;

    for (int c = tid; c < CDIM; c += 256)
        ln0[c] = ln1[(size_t)b * CDIM + c];
    __syncthreads();

    for (int h = 0; h < NH; h++) {
        const int d = tid >> 2, part = tid & 3;
        const float* wr = inw + (size_t)(h * HD + d) * CDIM;
        double s = 0.0;
        const int c0 = part * 192;
        for (int c = c0; c < c0 + 192; c++)
            s += (double)ln0[c] * (double)wr[c];
        s += __shfl_xor_sync(0xffffffffu, s, 1);
        s += __shfl_xor_sync(0xffffffffu, s, 2);
        if (part == 0) q0a[h * HD + d] = s + (double)inb[h * HD + d];
    }
    __syncthreads();

    for (int h = 0; h < NH; h++) {
        for (int c = tid; c < CDIM; c += 256) {
            double s = 0.0;
            #pragma unroll 8
            for (int d = 0; d < HD; d++)
                s += q0a[h * HD + d]
                     * (double)inw[(size_t)(CDIM + h * HD + d) * CDIM + c];
            wv[h * CDIM + c] = s;
        }
    }
    if (tid < NH) {
        double bsum = 0.0;
        for (int d = 0; d < HD; d++)
            bsum += q0a[tid * HD + d] * (double)inb[CDIM + tid * HD + d];
        beta[tid] = bsum;
    }
    __syncthreads();

    for (int j = w; j < NTOK; j += 8) {
        const float* xr = ln1 + ((size_t)j * BATCH + b) * CDIM;
        double s[NH];
        #pragma unroll
        for (int h = 0; h < NH; h++) s[h] = 0.0;
        for (int c = lane; c < CDIM; c += 32) {
            const double xv = (double)xr[c];
            #pragma unroll
            for (int h = 0; h < NH; h++)
                s[h] += xv * wv[h * CDIM + c];
        }
        #pragma unroll
        for (int h = 0; h < NH; h++) {
            #pragma unroll
            for (int o = 16; o; o >>= 1)
                s[h] += __shfl_xor_sync(0xffffffffu, s[h], o);
            if (lane == 0) sj[h * NTOK + j] = (s[h] + beta[h]) * 0.125;
        }
    }
    __syncthreads();

    double acc = 0.0;
    for (int h = 0; h < NH; h++) {
        double v = (tid < NTOK) ? sj[h * NTOK + tid] : -1e300;
        #pragma unroll
        for (int o = 16; o; o >>= 1)
            v = fmax(v, __shfl_xor_sync(0xffffffffu, v, o));
        if (lane == 0) redd[w] = v;
        __syncthreads();
        double mx = redd[0];
        #pragma unroll
        for (int i = 1; i < 8; i++) mx = fmax(mx, redd[i]);
        const double e = (tid < NTOK) ? exp(sj[h * NTOK + tid] - mx) : 0.0;
        double sv = e;
        #pragma unroll
        for (int o = 16; o; o >>= 1)
            sv += __shfl_xor_sync(0xffffffffu, sv, o);
        __syncthreads();
        if (lane == 0) redd[w] = sv;
        __syncthreads();
        double S = 0.0;
        #pragma unroll
        for (int i = 0; i < 8; i++) S += redd[i];
        if (tid >= 1 && tid < NTOK) acc += e / S;
        __syncthreads();
    }
    if (tid >= 1 && tid < NTOK) {
        const float val = (float)(acc * (1.0 / NH));
        cls[(size_t)b * NP + (tid - 1)] = val;
        cv[tid - 1] = val;
    }
    __syncthreads();
    if (tid < NP) {
        const float mv = cv[tid];
        int r = 0;
        for (int j = 0; j < NP; j++) {
            const float vj = cv[j];
            r += (vj > mv) || (vj == mv && j < tid);
        }
        if (r < LKEEP) idx[b * LKEEP + r] = tid;
        else           comp[b * LKEEP + (r - LKEEP)] = tid;
    }
}

// ---------------- gather + fused ln2 ----------------------------------------
__global__ void gather_ln2_kernel(const float* __restrict__ xres,
                                  const int* __restrict__ idx,
                                  const int* __restrict__ comp,
                                  const float* __restrict__ cls,
                                  const float* __restrict__ gam,
                                  const float* __restrict__ bet,
                                  float* __restrict__ xnew,
                                  f16* __restrict__ ln2f)
{
    const int nn = blockIdx.x;
    const int b  = blockIdx.y;
    const int t  = threadIdx.x;
    const size_t rowo = (size_t)nn * BATCH + b;
    float* dst = xnew + rowo * CDIM;

    float v0, v1, v2;
    if (nn == 0) {
        const float* src = xres + (size_t)b * CDIM;
        v0 = src[t]; v1 = src[t + 256]; v2 = src[t + 512];
    } else if (nn <= LKEEP) {
        const int tok = 1 + idx[b * LKEEP + (nn - 1)];
        const float* src = xres + ((size_t)tok * BATCH + b) * CDIM;
        v0 = src[t]; v1 = src[t + 256]; v2 = src[t + 512];
    } else {
        v0 = v1 = v2 = 0.f;
        for (int q = 0; q < LKEEP; q++) {
            const int j = comp[b * LKEEP + q];
            const float w = cls[b * NP + j];
            const float* src = xres + ((size_t)(1 + j) * BATCH + b) * CDIM;
            v0 += src[t] * w; v1 += src[t + 256] * w; v2 += src[t + 512] * w;
        }
    }
    dst[t] = v0; dst[t + 256] = v1; dst[t + 512] = v2;

    float s  = v0 + v1 + v2;
    float ss = v0 * v0 + v1 * v1 + v2 * v2;
    __shared__ float red[16];
    #pragma unroll
    for (int o = 16; o; o >>= 1) {
        s  += __shfl_xor_sync(0xffffffffu, s,  o);
        ss += __shfl_xor_sync(0xffffffffu, ss, o);
    }
    const int warp = t >> 5, lane = t & 31;
    if (lane == 0) { red[warp] = s; red[warp + 8] = ss; }
    __syncthreads();
    float S = 0.f, SS = 0.f;
    #pragma unroll
    for (int i = 0; i < 8; i++) { S += red[i]; SS += red[i + 8]; }
    const float mu  = S * (1.f / CDIM);
    const float var = SS * (1.f / CDIM) - mu * mu;
    const float inv = rsqrtf(var + 1e-5f);

    f16* lr = ln2f + rowo * CDIM;
    lr[t]       = __float2half_rn((v0 - mu) * inv * gam[t]       + bet[t]);
    lr[t + 256] = __float2half_rn((v1 - mu) * inv * gam[t + 256] + bet[t + 256]);
    lr[t + 512] = __float2half_rn((v2 - mu) * inv * gam[t + 512] + bet[t + 512]);
}

// ---------------- launch (single stream, linear) -----------------------------
extern "C" void kernel_launch(void* const* d_in, const int* in_sizes, int n_in,
                              void* d_out, int out_size)
{
    const float* x     = (const float*)d_in[0];
    const float* ln1_g = (const float*)d_in[1];
    const float* ln1_b = (const float*)d_in[2];
    const float* in_w  = (const float*)d_in[3];
    const float* in_b  = (const float*)d_in[4];
    const float* ow    = (const float*)d_in[5];
    const float* ob    = (const float*)d_in[6];
    const float* ln2_g = (const float*)d_in[7];
    const float* ln2_b = (const float*)d_in[8];
    const float* fc_w  = (const float*)d_in[9];
    const float* fc_b  = (const float*)d_in[10];
    const float* pj_w  = (const float*)d_in[11];
    const float* pj_b  = (const float*)d_in[12];
    float* out = (float*)d_out;

    float *ln1, *xres, *cls, *xnew;
    int *idxp, *compp;
    f16 *ln1f, *qkvf, *attf, *ln2f, *fcf, *wf;
    cudaGetSymbolAddress((void**)&ln1,   g_ln1);
    cudaGetSymbolAddress((void**)&xres,  g_xres);
    cudaGetSymbolAddress((void**)&cls,   g_cls);
    cudaGetSymbolAddress((void**)&idxp,  g_idx);
    cudaGetSymbolAddress((void**)&compp, g_comp);
    cudaGetSymbolAddress((void**)&xnew,  g_xnew);
    cudaGetSymbolAddress((void**)&ln1f,  g_ln1f);
    cudaGetSymbolAddress((void**)&qkvf,  g_qkvf);
    cudaGetSymbolAddress((void**)&attf,  g_attf);
    cudaGetSymbolAddress((void**)&ln2f,  g_ln2f);
    cudaGetSymbolAddress((void**)&fcf,   g_fcf);
    cudaGetSymbolAddress((void**)&wf,    g_wf);

    cudaFuncSetAttribute(attn_kernel, cudaFuncAttributeMaxDynamicSharedMemorySize,
                         ATT_SMEM);
    cudaFuncSetAttribute(f16_gemm_kernel, cudaFuncAttributeMaxDynamicSharedMemorySize,
                         GSM);
    cudaFuncSetAttribute(cls_score_kernel, cudaFuncAttributeMaxDynamicSharedMemorySize,
                         CLS_SMEM);

    // 0) weights -> fp16
    convert_w_kernel<<<(3 * CDIM * CDIM / 4 + 255) / 256, 256>>>(
        in_w, wf + O_INW, 3 * CDIM * CDIM / 4);
    convert_w_kernel<<<(CDIM * CDIM / 4 + 255) / 256, 256>>>(
        ow, wf + O_OW, CDIM * CDIM / 4);
    convert_w_kernel<<<(4 * CDIM * CDIM / 4 + 255) / 256, 256>>>(
        fc_w, wf + O_FCW, 4 * CDIM * CDIM / 4);
    convert_w_kernel<<<(4 * CDIM * CDIM / 4 + 255) / 256, 256>>>(
        pj_w, wf + O_PJW, 4 * CDIM * CDIM / 4);

    // 1) ln1 (fp32 for cls path + fp16 for GEMM)
    ln_kernel<<<M1, 256>>>(x, ln1_g, ln1_b, ln1, ln1f);
    // 2) qkv = ln1 @ in_proj_w^T + b -> fp16
    f16_gemm_kernel<<<dim3(3 * CDIM / 128, M1 / 128), 256, GSM>>>(
        ln1f, wf + O_INW, in_b, nullptr,
        nullptr, qkvf, M1, 3 * CDIM, CDIM, 0);
    // 3) tensor-core attention -> att fp16
    attn_kernel<<<dim3(BATCH, NH), 256, ATT_SMEM>>>(qkvf, attf);
    // 4) CLS scores in fp64 (single-pass all heads) + fused top-k
    cls_score_kernel<<<BATCH, 256, CLS_SMEM>>>(ln1, in_w, in_b, cls, idxp, compp);
    // 5) out_proj + residual x -> xres
    f16_gemm_kernel<<<dim3(CDIM / 128, M1 / 128), 256, GSM>>>(
        attf, wf + O_OW, ob, x,
        xres, nullptr, M1, CDIM, CDIM, 0);
    // 6) build x_new + fused ln2
    gather_ln2_kernel<<<dim3(NNEW, BATCH), 256>>>(
        xres, idxp, compp, cls, ln2_g, ln2_b, xnew, ln2f);
    // 7) fc + quickgelu (f16x2 tanh) -> fp16
    f16_gemm_kernel<<<dim3(4 * CDIM / 128, M2 / 128), 256, GSM>>>(
        ln2f, wf + O_FCW, fc_b, nullptr,
        nullptr, fcf, M2, 4 * CDIM, CDIM, 1);
    // 8) proj + residual x_new -> out
    f16_gemm_kernel<<<dim3(CDIM / 128, M2 / 128), 256, GSM>>>(
        fcf, wf + O_PJW, pj_b, xnew,
        out, nullptr, M2, CDIM, 4 * CDIM, 0);
}

// round 17
// speedup vs baseline: 1.0058x; 1.0058x over previous
#include <cuda_runtime.h>
#include <cuda_fp16.h>
#include <math.h>
#include <stdint.h>

#define NTOK  197
#define BATCH 256
#define CDIM  768
#define NH    12
#define HD    64
#define LKEEP 98
#define NP    (NTOK - 1)     // 196
#define NNEW  (LKEEP + 2)    // 100
#define M1    (NTOK * BATCH) // 50432
#define M2    (NNEW * BATCH) // 25600

typedef __half f16;

// ---------------- scratch (device globals; no cudaMalloc allowed) ----------
__device__ float g_ln1 [(size_t)M1 * CDIM];          // fp32 (cls path)
__device__ float g_xres[(size_t)M1 * CDIM];
__device__ float g_cls [(size_t)BATCH * NP];
__device__ int   g_idx [BATCH * LKEEP];
__device__ int   g_comp[BATCH * LKEEP];
__device__ float g_xnew[(size_t)M2 * CDIM];

__device__ f16 g_ln1f[(size_t)M1 * CDIM];
__device__ f16 g_qkvf[(size_t)M1 * 3 * CDIM];
__device__ f16 g_attf[(size_t)M1 * CDIM];
__device__ f16 g_ln2f[(size_t)M2 * CDIM];
__device__ f16 g_fcf [(size_t)M2 * 4 * CDIM];
// weights concatenated: in_w | out_w | fc_w | pj_w  (single fp16)
#define O_INW 0
#define O_OW  (3 * CDIM * CDIM)
#define O_FCW (O_OW + CDIM * CDIM)
#define O_PJW (O_FCW + 4 * CDIM * CDIM)
#define W_TOT (O_PJW + 4 * CDIM * CDIM)
__device__ f16 g_wf[W_TOT];

// ---------------- helpers ----------------------------------------------------
__device__ __forceinline__ uint32_t smem_u32(const void* p) {
    uint32_t a;
    asm("{ .reg .u64 t; cvta.to.shared.u64 t, %1; cvt.u32.u64 %0, t; }"
        : "=r"(a) : "l"(p));
    return a;
}
__device__ __forceinline__ void ldsm4(uint32_t r[4], uint32_t addr) {
    asm volatile("ldmatrix.sync.aligned.m8n8.x4.shared.b16 {%0,%1,%2,%3}, [%4];"
        : "=r"(r[0]), "=r"(r[1]), "=r"(r[2]), "=r"(r[3]) : "r"(addr));
}
__device__ __forceinline__ void ldsm4t(uint32_t r[4], uint32_t addr) {
    asm volatile("ldmatrix.sync.aligned.m8n8.x4.trans.shared.b16 {%0,%1,%2,%3}, [%4];"
        : "=r"(r[0]), "=r"(r[1]), "=r"(r[2]), "=r"(r[3]) : "r"(addr));
}
__device__ __forceinline__ void mma_f16(float c[4], const uint32_t a[4],
                                        const uint32_t b[2]) {
    asm volatile("mma.sync.aligned.m16n8k16.row.col.f32.f16.f16.f32 "
        "{%0,%1,%2,%3}, {%4,%5,%6,%7}, {%8,%9}, {%0,%1,%2,%3};"
        : "+f"(c[0]), "+f"(c[1]), "+f"(c[2]), "+f"(c[3])
        : "r"(a[0]), "r"(a[1]), "r"(a[2]), "r"(a[3]), "r"(b[0]), "r"(b[1]));
}
__device__ __forceinline__ void cp16(uint32_t dst, const void* src) {
    asm volatile("cp.async.cg.shared.global [%0], [%1], 16;"
                 :: "r"(dst), "l"(src));
}
__device__ __forceinline__ uint32_t pack_h2(float a, float b) {
    __half2 h = __floats2half2_rn(a, b);
    return *reinterpret_cast<uint32_t*>(&h);
}
// quick_gelu via single-MUFU tanh: x*sigmoid(1.702x) = x*0.5*(1+tanh(0.851x))
__device__ __forceinline__ float qgelu(float x) {
    float t;
    asm("tanh.approx.f32 %0, %1;" : "=f"(t) : "f"(0.851f * x));
    return x * 0.5f * (1.f + t);
}

// ---------------- fp32 -> fp16 converter -------------------------------------
__global__ void convert_w_kernel(const float* __restrict__ s,
                                 f16* __restrict__ d, int n4)
{
    const int i = blockIdx.x * 256 + threadIdx.x;
    if (i >= n4) return;
    float4 v = ((const float4*)s)[i];
    ((__half2*)d)[2 * i]     = __floats2half2_rn(v.x, v.y);
    ((__half2*)d)[2 * i + 1] = __floats2half2_rn(v.z, v.w);
}

// ---------------- layernorm: one block per row of 768 ----------------------
__global__ void ln_kernel(const float* __restrict__ x,
                          const float* __restrict__ gam,
                          const float* __restrict__ bet,
                          float* __restrict__ y,
                          f16* __restrict__ yf)
{
    const int row = blockIdx.x;
    const int t   = threadIdx.x;
    const float* xr = x + (size_t)row * CDIM;

    float v0 = xr[t], v1 = xr[t + 256], v2 = xr[t + 512];
    float s  = v0 + v1 + v2;
    float ss = v0 * v0 + v1 * v1 + v2 * v2;

    __shared__ float red[16];
    #pragma unroll
    for (int o = 16; o; o >>= 1) {
        s  += __shfl_xor_sync(0xffffffffu, s,  o);
        ss += __shfl_xor_sync(0xffffffffu, ss, o);
    }
    const int warp = t >> 5, lane = t & 31;
    if (lane == 0) { red[warp] = s; red[warp + 8] = ss; }
    __syncthreads();
    float S = 0.f, SS = 0.f;
    #pragma unroll
    for (int i = 0; i < 8; i++) { S += red[i]; SS += red[i + 8]; }

    const float mu  = S * (1.f / CDIM);
    const float var = SS * (1.f / CDIM) - mu * mu;
    const float inv = rsqrtf(var + 1e-5f);

    const size_t base = (size_t)row * CDIM;
    #pragma unroll
    for (int e = 0; e < 3; e++) {
        const int c = t + e * 256;
        const float v = (e == 0 ? v0 : (e == 1 ? v1 : v2));
        const float o = (v - mu) * inv * gam[c] + bet[c];
        if (y) y[base + c] = o;
        yf[base + c] = __float2half_rn(o);
    }
}

// ---------------- fp16 mma.sync GEMM, 4-stage, paired-chunk mainloop --------
// Two K-chunks per wait_group/__syncthreads: half the barrier frequency.
#define ROWB   80
#define TBYTES (128 * ROWB)
#define STG    (2 * TBYTES)
#define NSTAGE 4
#define GSM    (NSTAGE * STG)

__global__ void __launch_bounds__(256, 2)
f16_gemm_kernel(const f16* __restrict__ Af, const f16* __restrict__ Wf,
                const float* __restrict__ bias, const float* __restrict__ res,
                float* __restrict__ Cf, f16* __restrict__ Ch,
                int M, int Nn, int K, int act)
{
    extern __shared__ char dsm[];
    const uint32_t sb = smem_u32(dsm);

    const int tid = threadIdx.x, lane = tid & 31, wid = tid >> 5;
    const int wm = wid >> 2, wn = wid & 3;
    const int m0 = blockIdx.y * 128, n0 = blockIdx.x * 128;

    float acc[4][4][4] = {};

    auto issue = [&](int s, int t) {
        const int k0 = t << 5;
        #pragma unroll
        for (int r = 0; r < 4; r++) {
            const int id = tid + (r << 8);
            const int tensor = id >> 9;
            const int w = id & 511;
            const int row = w >> 2, c4 = w & 3;
            const f16* src = (tensor == 0)
                ? Af + (size_t)(m0 + row) * K + k0 + c4 * 8
                : Wf + (size_t)(n0 + row) * K + k0 + c4 * 8;
            const uint32_t dst = sb + (uint32_t)(s * STG + tensor * TBYTES
                                                 + row * ROWB + c4 * 16);
            cp16(dst, src);
        }
        asm volatile("cp.async.commit_group;" ::: "memory");
    };

    auto compute = [&](int s) {
        const uint32_t sA = sb + (uint32_t)(s * STG);
        #pragma unroll
        for (int ks = 0; ks < 2; ks++) {
            uint32_t ah[4][4];
            #pragma unroll
            for (int mf = 0; mf < 4; mf++) {
                const uint32_t ra = sA +
                    (uint32_t)((wm * 64 + mf * 16 + (lane & 15)) * ROWB
                               + ks * 32 + ((lane >> 4) << 4));
                ldsm4(ah[mf], ra);
            }
            #pragma unroll
            for (int pair = 0; pair < 2; pair++) {
                uint32_t bh4[4];
                const uint32_t rb = sA + TBYTES +
                    (uint32_t)((wn * 32 + pair * 16 + (lane & 7)
                                + ((lane >> 4) << 3)) * ROWB
                               + ks * 32 + (((lane >> 3) & 1) << 4));
                ldsm4(bh4, rb);
                #pragma unroll
                for (int mf = 0; mf < 4; mf++) {
                    mma_f16(acc[mf][pair * 2],     ah[mf], bh4);
                    mma_f16(acc[mf][pair * 2 + 1], ah[mf], bh4 + 2);
                }
            }
        }
    };

    const int nch = K >> 5;              // 24 or 96 (always even)
    issue(0, 0);
    issue(1, 1);

    for (int t = 0; t < nch; t += 2) {
        asm volatile("cp.async.wait_group 0;" ::: "memory");  // t, t+1 landed
        __syncthreads();                 // all warps done reading old stages
        if (t + 2 < nch) {               // prefetch next pair under compute
            issue((t + 2) & 3, t + 2);
            issue((t + 3) & 3, t + 3);
        }
        compute(t & 3);
        compute((t + 1) & 3);
    }

    #pragma unroll
    for (int mf = 0; mf < 4; mf++) {
        #pragma unroll
        for (int nf = 0; nf < 4; nf++) {
            const int rr = m0 + wm * 64 + mf * 16 + (lane >> 2);
            const int cc = n0 + wn * 32 + nf * 8 + ((lane & 3) << 1);
            const float b0 = bias[cc], b1 = bias[cc + 1];
            float v0 = acc[mf][nf][0] + b0;
            float v1 = acc[mf][nf][1] + b1;
            float v2 = acc[mf][nf][2] + b0;
            float v3 = acc[mf][nf][3] + b1;
            if (act) {
                v0 = qgelu(v0); v1 = qgelu(v1);
                v2 = qgelu(v2); v3 = qgelu(v3);
            }
            const size_t o0 = (size_t)rr * Nn + cc;
            const size_t o1 = (size_t)(rr + 8) * Nn + cc;
            if (Cf) {
                if (res) {
                    float2 r0 = *(const float2*)(res + o0);
                    float2 r1 = *(const float2*)(res + o1);
                    v0 += r0.x; v1 += r0.y; v2 += r1.x; v3 += r1.y;
                }
                float2 s0; s0.x = v0; s0.y = v1;
                float2 s1; s1.x = v2; s1.y = v3;
                *(float2*)(Cf + o0) = s0;
                *(float2*)(Cf + o1) = s1;
            } else {
                *(__half2*)(Ch + o0) = __floats2half2_rn(v0, v1);
                *(__half2*)(Ch + o1) = __floats2half2_rn(v2, v3);
            }
        }
    }
}

// ---------------- tensor-core attention: one CTA per (b,h) ------------------
#define TP   208
#define QP   72
#define ATT_SMEM (3 * TP * QP * 2)     // 89856 bytes

__global__ void __launch_bounds__(256)
attn_kernel(const f16* __restrict__ qkvf, f16* __restrict__ outf)
{
    extern __shared__ f16 smh[];
    f16* Qs = smh;
    f16* Ks = Qs + TP * QP;
    f16* Vs = Ks + TP * QP;

    const int b = blockIdx.x, h = blockIdx.y;
    const int tid = threadIdx.x, lane = tid & 31, warp = tid >> 5;
    const uint32_t sQ = smem_u32(Qs), sK = smem_u32(Ks), sV = smem_u32(Vs);

    for (int it = tid; it < TP * 8 * 3; it += 256) {
        const int t = it / (TP * 8);
        const int rem = it % (TP * 8);
        const int j = rem >> 3, c = rem & 7;
        f16* dst = (t == 0 ? Qs : (t == 1 ? Ks : Vs)) + j * QP + c * 8;
        if (j < NTOK) {
            const f16* src = qkvf + ((size_t)j * BATCH + b) * (3 * CDIM)
                             + t * CDIM + h * HD + c * 8;
            *(uint4*)dst = *(const uint4*)src;
        } else {
            uint4 z; z.x = z.y = z.z = z.w = 0u;
            *(uint4*)dst = z;
        }
    }
    __syncthreads();

    for (int mt = warp; mt < 13; mt += 8) {
        const int mbase = mt * 16;

        uint32_t aq[4][4];
        #pragma unroll
        for (int ks = 0; ks < 4; ks++) {
            const uint32_t ra = sQ + (uint32_t)(((mbase + (lane & 15)) * QP
                                + ks * 16 + ((lane >> 4) << 3)) * 2);
            ldsm4(aq[ks], ra);
        }

        float sacc[26][4];
        #pragma unroll
        for (int nt = 0; nt < 26; nt++)
            #pragma unroll
            for (int q = 0; q < 4; q++) sacc[nt][q] = 0.f;
        #pragma unroll
        for (int np = 0; np < 13; np++) {
            #pragma unroll
            for (int ks = 0; ks < 4; ks++) {
                uint32_t bk[4];
                const uint32_t rb = sK + (uint32_t)(((np * 16 + (lane & 7)
                                    + ((lane >> 4) << 3)) * QP
                                    + ks * 16 + (((lane >> 3) & 1) << 3)) * 2);
                ldsm4(bk, rb);
                mma_f16(sacc[np * 2],     aq[ks], bk);
                mma_f16(sacc[np * 2 + 1], aq[ks], bk + 2);
            }
        }

        float mx0 = -1e30f, mx1 = -1e30f;
        #pragma unroll
        for (int nt = 0; nt < 26; nt++) {
            const int c = nt * 8 + ((lane & 3) << 1);
            sacc[nt][0] = (c     < NTOK) ? sacc[nt][0] * 0.125f : -1e30f;
            sacc[nt][1] = (c + 1 < NTOK) ? sacc[nt][1] * 0.125f : -1e30f;
            sacc[nt][2] = (c     < NTOK) ? sacc[nt][2] * 0.125f : -1e30f;
            sacc[nt][3] = (c + 1 < NTOK) ? sacc[nt][3] * 0.125f : -1e30f;
            mx0 = fmaxf(mx0, fmaxf(sacc[nt][0], sacc[nt][1]));
            mx1 = fmaxf(mx1, fmaxf(sacc[nt][2], sacc[nt][3]));
        }
        mx0 = fmaxf(mx0, __shfl_xor_sync(0xffffffffu, mx0, 1));
        mx0 = fmaxf(mx0, __shfl_xor_sync(0xffffffffu, mx0, 2));
        mx1 = fmaxf(mx1, __shfl_xor_sync(0xffffffffu, mx1, 1));
        mx1 = fmaxf(mx1, __shfl_xor_sync(0xffffffffu, mx1, 2));
        float sm0 = 0.f, sm1 = 0.f;
        #pragma unroll
        for (int nt = 0; nt < 26; nt++) {
            sacc[nt][0] = __expf(sacc[nt][0] - mx0);
            sacc[nt][1] = __expf(sacc[nt][1] - mx0);
            sacc[nt][2] = __expf(sacc[nt][2] - mx1);
            sacc[nt][3] = __expf(sacc[nt][3] - mx1);
            sm0 += sacc[nt][0] + sacc[nt][1];
            sm1 += sacc[nt][2] + sacc[nt][3];
        }
        sm0 += __shfl_xor_sync(0xffffffffu, sm0, 1);
        sm0 += __shfl_xor_sync(0xffffffffu, sm0, 2);
        sm1 += __shfl_xor_sync(0xffffffffu, sm1, 1);
        sm1 += __shfl_xor_sync(0xffffffffu, sm1, 2);
        const float inv0 = 1.f / sm0, inv1 = 1.f / sm1;

        float oacc[8][4];
        #pragma unroll
        for (int nt = 0; nt < 8; nt++)
            #pragma unroll
            for (int q = 0; q < 4; q++) oacc[nt][q] = 0.f;
        #pragma unroll
        for (int kt = 0; kt < 13; kt++) {
            uint32_t ap[4];
            ap[0] = pack_h2(sacc[2 * kt][0] * inv0, sacc[2 * kt][1] * inv0);
            ap[1] = pack_h2(sacc[2 * kt][2] * inv1, sacc[2 * kt][3] * inv1);
            ap[2] = pack_h2(sacc[2 * kt + 1][0] * inv0, sacc[2 * kt + 1][1] * inv0);
            ap[3] = pack_h2(sacc[2 * kt + 1][2] * inv1, sacc[2 * kt + 1][3] * inv1);
            #pragma unroll
            for (int np = 0; np < 4; np++) {
                uint32_t bv[4];
                const uint32_t va = sV + (uint32_t)(((kt * 16 + (lane & 15)) * QP
                                    + np * 16 + ((lane >> 4) << 3)) * 2);
                ldsm4t(bv, va);
                mma_f16(oacc[np * 2],     ap, bv);
                mma_f16(oacc[np * 2 + 1], ap, bv + 2);
            }
        }

        const int r0 = mbase + (lane >> 2), r1 = r0 + 8;
        #pragma unroll
        for (int nt = 0; nt < 8; nt++) {
            const int c = h * HD + nt * 8 + ((lane & 3) << 1);
            if (r0 < NTOK)
                *(__half2*)(outf + ((size_t)r0 * BATCH + b) * CDIM + c) =
                    __floats2half2_rn(oacc[nt][0], oacc[nt][1]);
            if (r1 < NTOK)
                *(__half2*)(outf + ((size_t)r1 * BATCH + b) * CDIM + c) =
                    __floats2half2_rn(oacc[nt][2], oacc[nt][3]);
        }
    }
}

// ---------------- CLS scores (fp64, all heads single-pass) + fused top-k ----
#define CLS_SMEM (((NH * HD) + (NH * CDIM) + (NH * NTOK) + NH + 8) * 8 \
                  + (CDIM + NP) * 4)

__global__ void __launch_bounds__(256)
cls_score_kernel(const float* __restrict__ ln1, const float* __restrict__ inw,
                 const float* __restrict__ inb, float* __restrict__ cls,
                 int* __restrict__ idx, int* __restrict__ comp)
{
    extern __shared__ double dsm2[];
    double* q0a  = dsm2;                 // [NH][HD]
    double* wv   = q0a + NH * HD;        // [NH][CDIM]
    double* sj   = wv + NH * CDIM;       // [NH][NTOK]
    double* beta = sj + NH * NTOK;       // [NH]
    double* redd = beta + NH;            // [8]
    float*  ln0  = (float*)(redd + 8);   // [CDIM]
    float*  cv   = ln0 + CDIM;           // [NP]

    const int b = blockIdx.x, tid = threadIdx.x;
    const int lane = tid & 31, w = tid >> 5;

    for (int c = tid; c < CDIM; c += 256)
        ln0[c] = ln1[(size_t)b * CDIM + c];
    __syncthreads();

    for (int h = 0; h < NH; h++) {
        const int d = tid >> 2, part = tid & 3;
        const float* wr = inw + (size_t)(h * HD + d) * CDIM;
        double s = 0.0;
        const int c0 = part * 192;
        for (int c = c0; c < c0 + 192; c++)
            s += (double)ln0[c] * (double)wr[c];
        s += __shfl_xor_sync(0xffffffffu, s, 1);
        s += __shfl_xor_sync(0xffffffffu, s, 2);
        if (part == 0) q0a[h * HD + d] = s + (double)inb[h * HD + d];
    }
    __syncthreads();

    for (int h = 0; h < NH; h++) {
        for (int c = tid; c < CDIM; c += 256) {
            double s = 0.0;
            #pragma unroll 8
            for (int d = 0; d < HD; d++)
                s += q0a[h * HD + d]
                     * (double)inw[(size_t)(CDIM + h * HD + d) * CDIM + c];
            wv[h * CDIM + c] = s;
        }
    }
    if (tid < NH) {
        double bsum = 0.0;
        for (int d = 0; d < HD; d++)
            bsum += q0a[tid * HD + d] * (double)inb[CDIM + tid * HD + d];
        beta[tid] = bsum;
    }
    __syncthreads();

    for (int j = w; j < NTOK; j += 8) {
        const float* xr = ln1 + ((size_t)j * BATCH + b) * CDIM;
        double s[NH];
        #pragma unroll
        for (int h = 0; h < NH; h++) s[h] = 0.0;
        for (int c = lane; c < CDIM; c += 32) {
            const double xv = (double)xr[c];
            #pragma unroll
            for (int h = 0; h < NH; h++)
                s[h] += xv * wv[h * CDIM + c];
        }
        #pragma unroll
        for (int h = 0; h < NH; h++) {
            #pragma unroll
            for (int o = 16; o; o >>= 1)
                s[h] += __shfl_xor_sync(0xffffffffu, s[h], o);
            if (lane == 0) sj[h * NTOK + j] = (s[h] + beta[h]) * 0.125;
        }
    }
    __syncthreads();

    double acc = 0.0;
    for (int h = 0; h < NH; h++) {
        double v = (tid < NTOK) ? sj[h * NTOK + tid] : -1e300;
        #pragma unroll
        for (int o = 16; o; o >>= 1)
            v = fmax(v, __shfl_xor_sync(0xffffffffu, v, o));
        if (lane == 0) redd[w] = v;
        __syncthreads();
        double mx = redd[0];
        #pragma unroll
        for (int i = 1; i < 8; i++) mx = fmax(mx, redd[i]);
        const double e = (tid < NTOK) ? exp(sj[h * NTOK + tid] - mx) : 0.0;
        double sv = e;
        #pragma unroll
        for (int o = 16; o; o >>= 1)
            sv += __shfl_xor_sync(0xffffffffu, sv, o);
        __syncthreads();
        if (lane == 0) redd[w] = sv;
        __syncthreads();
        double S = 0.0;
        #pragma unroll
        for (int i = 0; i < 8; i++) S += redd[i];
        if (tid >= 1 && tid < NTOK) acc += e / S;
        __syncthreads();
    }
    if (tid >= 1 && tid < NTOK) {
        const float val = (float)(acc * (1.0 / NH));
        cls[(size_t)b * NP + (tid - 1)] = val;
        cv[tid - 1] = val;
    }
    __syncthreads();
    if (tid < NP) {
        const float mv = cv[tid];
        int r = 0;
        for (int j = 0; j < NP; j++) {
            const float vj = cv[j];
            r += (vj > mv) || (vj == mv && j < tid);
        }
        if (r < LKEEP) idx[b * LKEEP + r] = tid;
        else           comp[b * LKEEP + (r - LKEEP)] = tid;
    }
}

// ---------------- gather + fused ln2 ----------------------------------------
__global__ void gather_ln2_kernel(const float* __restrict__ xres,
                                  const int* __restrict__ idx,
                                  const int* __restrict__ comp,
                                  const float* __restrict__ cls,
                                  const float* __restrict__ gam,
                                  const float* __restrict__ bet,
                                  float* __restrict__ xnew,
                                  f16* __restrict__ ln2f)
{
    const int nn = blockIdx.x;
    const int b  = blockIdx.y;
    const int t  = threadIdx.x;
    const size_t rowo = (size_t)nn * BATCH + b;
    float* dst = xnew + rowo * CDIM;

    float v0, v1, v2;
    if (nn == 0) {
        const float* src = xres + (size_t)b * CDIM;
        v0 = src[t]; v1 = src[t + 256]; v2 = src[t + 512];
    } else if (nn <= LKEEP) {
        const int tok = 1 + idx[b * LKEEP + (nn - 1)];
        const float* src = xres + ((size_t)tok * BATCH + b) * CDIM;
        v0 = src[t]; v1 = src[t + 256]; v2 = src[t + 512];
    } else {
        v0 = v1 = v2 = 0.f;
        for (int q = 0; q < LKEEP; q++) {
            const int j = comp[b * LKEEP + q];
            const float w = cls[b * NP + j];
            const float* src = xres + ((size_t)(1 + j) * BATCH + b) * CDIM;
            v0 += src[t] * w; v1 += src[t + 256] * w; v2 += src[t + 512] * w;
        }
    }
    dst[t] = v0; dst[t + 256] = v1; dst[t + 512] = v2;

    float s  = v0 + v1 + v2;
    float ss = v0 * v0 + v1 * v1 + v2 * v2;
    __shared__ float red[16];
    #pragma unroll
    for (int o = 16; o; o >>= 1) {
        s  += __shfl_xor_sync(0xffffffffu, s,  o);
        ss += __shfl_xor_sync(0xffffffffu, ss, o);
    }
    const int warp = t >> 5, lane = t & 31;
    if (lane == 0) { red[warp] = s; red[warp + 8] = ss; }
    __syncthreads();
    float S = 0.f, SS = 0.f;
    #pragma unroll
    for (int i = 0; i < 8; i++) { S += red[i]; SS += red[i + 8]; }
    const float mu  = S * (1.f / CDIM);
    const float var = SS * (1.f / CDIM) - mu * mu;
    const float inv = rsqrtf(var + 1e-5f);

    f16* lr = ln2f + rowo * CDIM;
    lr[t]       = __float2half_rn((v0 - mu) * inv * gam[t]       + bet[t]);
    lr[t + 256] = __float2half_rn((v1 - mu) * inv * gam[t + 256] + bet[t + 256]);
    lr[t + 512] = __float2half_rn((v2 - mu) * inv * gam[t + 512] + bet[t + 512]);
}

// ---------------- launch (single stream, linear) -----------------------------
extern "C" void kernel_launch(void* const* d_in, const int* in_sizes, int n_in,
                              void* d_out, int out_size)
{
    const float* x     = (const float*)d_in[0];
    const float* ln1_g = (const float*)d_in[1];
    const float* ln1_b = (const float*)d_in[2];
    const float* in_w  = (const float*)d_in[3];
    const float* in_b  = (const float*)d_in[4];
    const float* ow    = (const float*)d_in[5];
    const float* ob    = (const float*)d_in[6];
    const float* ln2_g = (const float*)d_in[7];
    const float* ln2_b = (const float*)d_in[8];
    const float* fc_w  = (const float*)d_in[9];
    const float* fc_b  = (const float*)d_in[10];
    const float* pj_w  = (const float*)d_in[11];
    const float* pj_b  = (const float*)d_in[12];
    float* out = (float*)d_out;

    float *ln1, *xres, *cls, *xnew;
    int *idxp, *compp;
    f16 *ln1f, *qkvf, *attf, *ln2f, *fcf, *wf;
    cudaGetSymbolAddress((void**)&ln1,   g_ln1);
    cudaGetSymbolAddress((void**)&xres,  g_xres);
    cudaGetSymbolAddress((void**)&cls,   g_cls);
    cudaGetSymbolAddress((void**)&idxp,  g_idx);
    cudaGetSymbolAddress((void**)&compp, g_comp);
    cudaGetSymbolAddress((void**)&xnew,  g_xnew);
    cudaGetSymbolAddress((void**)&ln1f,  g_ln1f);
    cudaGetSymbolAddress((void**)&qkvf,  g_qkvf);
    cudaGetSymbolAddress((void**)&attf,  g_attf);
    cudaGetSymbolAddress((void**)&ln2f,  g_ln2f);
    cudaGetSymbolAddress((void**)&fcf,   g_fcf);
    cudaGetSymbolAddress((void**)&wf,    g_wf);

    cudaFuncSetAttribute(attn_kernel, cudaFuncAttributeMaxDynamicSharedMemorySize,
                         ATT_SMEM);
    cudaFuncSetAttribute(f16_gemm_kernel, cudaFuncAttributeMaxDynamicSharedMemorySize,
                         GSM);
    cudaFuncSetAttribute(cls_score_kernel, cudaFuncAttributeMaxDynamicSharedMemorySize,
                         CLS_SMEM);

    // 0) weights -> fp16
    convert_w_kernel<<<(3 * CDIM * CDIM / 4 + 255) / 256, 256>>>(
        in_w, wf + O_INW, 3 * CDIM * CDIM / 4);
    convert_w_kernel<<<(CDIM * CDIM / 4 + 255) / 256, 256>>>(
        ow, wf + O_OW, CDIM * CDIM / 4);
    convert_w_kernel<<<(4 * CDIM * CDIM / 4 + 255) / 256, 256>>>(
        fc_w, wf + O_FCW, 4 * CDIM * CDIM / 4);
    convert_w_kernel<<<(4 * CDIM * CDIM / 4 + 255) / 256, 256>>>(
        pj_w, wf + O_PJW, 4 * CDIM * CDIM / 4);

    // 1) ln1 (fp32 for cls path + fp16 for GEMM)
    ln_kernel<<<M1, 256>>>(x, ln1_g, ln1_b, ln1, ln1f);
    // 2) qkv = ln1 @ in_proj_w^T + b -> fp16
    f16_gemm_kernel<<<dim3(3 * CDIM / 128, M1 / 128), 256, GSM>>>(
        ln1f, wf + O_INW, in_b, nullptr,
        nullptr, qkvf, M1, 3 * CDIM, CDIM, 0);
    // 3) tensor-core attention -> att fp16
    attn_kernel<<<dim3(BATCH, NH), 256, ATT_SMEM>>>(qkvf, attf);
    // 4) CLS scores in fp64 (single-pass all heads) + fused top-k
    cls_score_kernel<<<BATCH, 256, CLS_SMEM>>>(ln1, in_w, in_b, cls, idxp, compp);
    // 5) out_proj + residual x -> xres
    f16_gemm_kernel<<<dim3(CDIM / 128, M1 / 128), 256, GSM>>>(
        attf, wf + O_OW, ob, x,
        xres, nullptr, M1, CDIM, CDIM, 0);
    // 6) build x_new + fused ln2
    gather_ln2_kernel<<<dim3(NNEW, BATCH), 256>>>(
        xres, idxp, compp, cls, ln2_g, ln2_b, xnew, ln2f);
    // 7) fc + quickgelu -> fp16
    f16_gemm_kernel<<<dim3(4 * CDIM / 128, M2 / 128), 256, GSM>>>(
        ln2f, wf + O_FCW, fc_b, nullptr,
        nullptr, fcf, M2, 4 * CDIM, CDIM, 1);
    // 8) proj + residual x_new -> out
    f16_gemm_kernel<<<dim3(CDIM / 128, M2 / 128), 256, GSM>>>(
        fcf, wf + O_PJW, pj_b, xnew,
        out, nullptr, M2, CDIM, 4 * CDIM, 0);
}